// round 11
// baseline (speedup 1.0000x reference)
#include <cuda_runtime.h>
#include <cuda_fp16.h>
#include <math.h>
#include <stdint.h>

// ---------------------------------------------------------------------------
// StarTransformer: B=8, L=2048, H=512, NH=8, HD=64, NUM_LAYERS=4
// GEMMs via mma.sync fp16 (HMMA) + ldmatrix, single-term fp16.
// R11: CTA 128x128, warp 64x32 — 6 LDSM per 16 MMA (was 5 per 8).
// ---------------------------------------------------------------------------
#define BB   8
#define LL   2048
#define LP1  2049
#define HH   512
#define NHD  8
#define HD   64
#define NL   4
#define NSLOT 17        // fc_w + 4 layers x (wq,wk,wv,ring_wo)

// -------------------- scratch (device globals, no allocs) -------------------
__device__ float g_nodes[BB * LL * HH];
__device__ float g_q   [BB * LP1 * HH];
__device__ float g_k   [BB * LP1 * HH];
__device__ float g_v   [BB * LP1 * HH];
__device__ float g_relay[BB * HH];
__device__ float g_attr [BB * HH];
__device__ float g_part [BB * 16 * HH];

__device__ __half g_data[BB * LL * HH];
__device__ __half g_xy  [BB * LP1 * HH];
__device__ __half g_att [BB * LL * HH];
__device__ __half g_wt  [NSLOT * HH * HH];   // W^T [n][k], fp16

// ------------------------------ helpers -------------------------------------
__device__ __forceinline__ uint32_t smem_u32(const void* p) {
    uint32_t a;
    asm("{ .reg .u64 t; cvta.to.shared.u64 t, %1; cvt.u32.u64 %0, t; }"
        : "=r"(a) : "l"(p));
    return a;
}
__device__ __forceinline__ void cp_async16(uint32_t dst, const void* src, uint32_t sz) {
    asm volatile("cp.async.cg.shared.global [%0], [%1], 16, %2;"
                 :: "r"(dst), "l"(src), "r"(sz));
}
#define CP_COMMIT() asm volatile("cp.async.commit_group;" ::: "memory")
#define CP_WAIT(n)  asm volatile("cp.async.wait_group %0;" :: "n"(n) : "memory")

__device__ __forceinline__ void ldsm_x4(uint32_t* r, uint32_t addr) {
    asm volatile("ldmatrix.sync.aligned.m8n8.x4.shared.b16 {%0,%1,%2,%3}, [%4];"
        : "=r"(r[0]), "=r"(r[1]), "=r"(r[2]), "=r"(r[3]) : "r"(addr));
}
__device__ __forceinline__ void mma16816(float* c, const uint32_t* a,
                                         uint32_t b0, uint32_t b1) {
    asm volatile(
        "mma.sync.aligned.m16n8k16.row.col.f32.f16.f16.f32 "
        "{%0,%1,%2,%3}, {%4,%5,%6,%7}, {%8,%9}, {%0,%1,%2,%3};"
        : "+f"(c[0]), "+f"(c[1]), "+f"(c[2]), "+f"(c[3])
        : "r"(a[0]), "r"(a[1]), "r"(a[2]), "r"(a[3]), "r"(b0), "r"(b1));
}

// ------------------------ mma.sync GEMM kernel ------------------------------
// D[M x 512] = A[M x 512] @ W_slot^T + epilogue.
// CTA tile 128m x 128n, BK=32. 8 warps as 2(m) x 4(n): warp tile 64m x 32n.
// 3-stage cp.async pipeline; ONE __syncthreads per k-iter.
// MODE 0: emb  (A = data, C = nodes, EPI: +bias +pos)
// MODE 1: qkv  (A = xy, blockIdx.z -> q/k/v, EPI: +bias)
// MODE 2: ring (A = att, C = nodes, EPI: leaky_relu(+bias))
#define PADK 40                       // fp16 elems per smem row (32 + 8 pad)
#define A_SUB (128 * PADK * 2)        // 10240 B
#define B_SUB (128 * PADK * 2)        // 10240 B
#define STAGE_B (A_SUB + B_SUB)       // 20480 B: [A][B]
#define NSTAGE 3
#define GEMM_SMEM (NSTAGE * STAGE_B)  // 61440 B

template<int MODE>
__global__ __launch_bounds__(256, 2)
void mma_gemm(int layer, int M,
              const float* __restrict__ b0p, const float* __restrict__ b1p,
              const float* __restrict__ b2p, const float* __restrict__ pos)
{
    extern __shared__ __align__(128) char smem[];
    const uint32_t sb = smem_u32(smem);
    const int tid = threadIdx.x;
    const int lane = tid & 31, wid = tid >> 5;
    const int row0 = blockIdx.y * 128;
    const int col0 = blockIdx.x * 128;

    const __half* a_p;
    float* C;
    const float* bias;
    int slot;
    if (MODE == 0) { a_p = g_data; C = g_nodes; bias = b0p; slot = 0; }
    else if (MODE == 1) {
        const int z = blockIdx.z;
        a_p = g_xy;
        C    = (z == 0) ? g_q : (z == 1) ? g_k : g_v;
        bias = (z == 0) ? b0p : (z == 1) ? b1p : b2p;
        slot = 1 + layer * 4 + z;
    } else { a_p = g_att; C = g_nodes; bias = b0p; slot = 1 + layer * 4 + 3; }
    const __half* w_p = g_wt + (size_t)slot * HH * HH;

    // ---- stage loader: 1024 16B words (A 512, B 512) ----
    auto load_stage = [&](int stage, int kc) {
        const uint32_t stb = sb + stage * STAGE_B;
        #pragma unroll
        for (int it = 0; it < 4; ++it) {
            const int idx = it * 256 + tid;
            const int row = (idx & 511) >> 2;
            const int col = (idx & 3) * 8;
            uint32_t sz = 16;
            const __half* src;
            uint32_t doff;
            if (idx < 512) {           // A region
                const int gr = row0 + row;
                src = a_p + (size_t)gr * HH + kc + col;
                doff = 0u;
                if (gr >= M) { sz = 0; src = a_p; }
            } else {                   // B region (512 words, rows 0..127)
                src = w_p + (size_t)(col0 + row) * HH + kc + col;
                doff = A_SUB;
            }
            cp_async16(stb + doff + (uint32_t)(row * PADK + col) * 2, src, sz);
        }
        CP_COMMIT();
    };

    // warp tiling: 2(m) x 4(n)
    const int wm = (wid >> 2) * 64;     // 0 or 64
    const int wn = (wid & 3) * 32;      // 0,32,64,96

    // ldmatrix lane addressing
    const int lr = lane & 15;           // row within 16-row group
    const int lc = (lane >> 4) * 8;     // k offset 0 or 8

    float acc[4][4][4];
    #pragma unroll
    for (int mf = 0; mf < 4; ++mf)
        #pragma unroll
        for (int nf = 0; nf < 4; ++nf)
            #pragma unroll
            for (int e = 0; e < 4; ++e) acc[mf][nf][e] = 0.f;

    // prologue: fill stages 0..NSTAGE-2
    load_stage(0, 0);
    load_stage(1, 32);

    const int NT = HH / 32;   // 16
    for (int kt = 0; kt < NT; ++kt) {
        if (kt == NT - 1) { CP_WAIT(0); } else { CP_WAIT(1); }
        __syncthreads();

        if (kt + NSTAGE - 1 < NT)
            load_stage((kt + NSTAGE - 1) % NSTAGE, (kt + NSTAGE - 1) * 32);

        const uint32_t stb = sb + (kt % NSTAGE) * STAGE_B;
        const uint32_t sA = stb;
        const uint32_t sB = stb + A_SUB;

        #pragma unroll
        for (int ks = 0; ks < 2; ++ks) {
            const int k0 = ks * 16;
            uint32_t ah[4][4];
            #pragma unroll
            for (int mf = 0; mf < 4; ++mf) {
                const uint32_t ro = (uint32_t)((wm + mf * 16 + lr) * PADK + k0 + lc) * 2;
                ldsm_x4(ah[mf], sA + ro);
            }
            #pragma unroll
            for (int p = 0; p < 2; ++p) {
                uint32_t bh[4];
                const uint32_t ro = (uint32_t)((wn + p * 16 + lr) * PADK + k0 + lc) * 2;
                ldsm_x4(bh, sB + ro);
                const int nf0 = p * 2, nf1 = p * 2 + 1;
                #pragma unroll
                for (int mf = 0; mf < 4; ++mf) {
                    mma16816(acc[mf][nf0], ah[mf], bh[0], bh[2]);
                    mma16816(acc[mf][nf1], ah[mf], bh[1], bh[3]);
                }
            }
        }
    }

    // epilogue
    #pragma unroll
    for (int mf = 0; mf < 4; ++mf) {
        const int rlo = row0 + wm + mf * 16 + (lane >> 2);
        #pragma unroll
        for (int nf = 0; nf < 4; ++nf) {
            const int c = col0 + wn + nf * 8 + (lane & 3) * 2;
            const float bx = bias[c], by = bias[c + 1];
            #pragma unroll
            for (int hrow = 0; hrow < 2; ++hrow) {
                const int r = rlo + hrow * 8;
                if (r >= M) continue;
                float vx = acc[mf][nf][hrow * 2 + 0] + bx;
                float vy = acc[mf][nf][hrow * 2 + 1] + by;
                if (MODE == 0) {
                    const size_t po = (size_t)(r & (LL - 1)) * HH + c;
                    vx += pos[po];
                    vy += pos[po + 1];
                }
                if (MODE == 2) {
                    vx = (vx > 0.f) ? vx : 0.2f * vx;
                    vy = (vy > 0.f) ? vy : 0.2f * vy;
                }
                *(float2*)(C + (size_t)r * HH + c) = make_float2(vx, vy);
            }
        }
    }
}

// ------------------- weight transpose -> fp16 -------------------------------
__global__ void wconv_kernel(const float* __restrict__ fc_w, const float* __restrict__ wq,
                             const float* __restrict__ wk, const float* __restrict__ wv,
                             const float* __restrict__ ring_wo)
{
    const int z = blockIdx.z;
    const float* W;
    if (z == 0) W = fc_w;
    else {
        const int s = z - 1, layer = s >> 2, which = s & 3;
        const float* base = (which == 0) ? wq : (which == 1) ? wk
                          : (which == 2) ? wv : ring_wo;
        W = base + (size_t)layer * HH * HH;
    }
    __shared__ float t[32][33];
    const int x0 = blockIdx.x * 32, y0 = blockIdx.y * 32;
    const int tx = threadIdx.x, ty = threadIdx.y;   // (32,8)
    #pragma unroll
    for (int i = 0; i < 4; ++i)
        t[ty * 4 + i][tx] = W[(size_t)(y0 + ty * 4 + i) * HH + x0 + tx];
    __syncthreads();
    __half* wh = g_wt + (size_t)z * HH * HH;
    #pragma unroll
    for (int i = 0; i < 4; ++i) {
        const int n = x0 + ty * 4 + i, k = y0 + tx;
        wh[(size_t)n * HH + k] = __float2half_rn(t[tx][ty * 4 + i]);
    }
}

// ----------------------- data -> fp16 conversion (2 halves) -----------------
__global__ void aconv_a_kernel(const float* __restrict__ x)
{
    const int n4 = BB * LL * HH / 8;   // first half
    for (int i = blockIdx.x * blockDim.x + threadIdx.x; i < n4;
         i += gridDim.x * blockDim.x) {
        const float4 v = *(const float4*)(x + (size_t)i * 4);
        __half h[4];
        h[0] = __float2half_rn(v.x); h[1] = __float2half_rn(v.y);
        h[2] = __float2half_rn(v.z); h[3] = __float2half_rn(v.w);
        *(uint2*)(g_data + (size_t)i * 4) = *(uint2*)h;
    }
}
__global__ void aconv_b_kernel(const float* __restrict__ x)
{
    const int half = BB * LL * HH / 8;
    const int n4 = BB * LL * HH / 4;
    for (int i = half + blockIdx.x * blockDim.x + threadIdx.x; i < n4;
         i += gridDim.x * blockDim.x) {
        const float4 v = *(const float4*)(x + (size_t)i * 4);
        __half h[4];
        h[0] = __float2half_rn(v.x); h[1] = __float2half_rn(v.y);
        h[2] = __float2half_rn(v.z); h[3] = __float2half_rn(v.w);
        *(uint2*)(g_data + (size_t)i * 4) = *(uint2*)h;
    }
}

// ------------------------- relay init (column mean) -------------------------
__global__ void colmean_partial()
{
    const int b = blockIdx.x, chunk = blockIdx.y, c = threadIdx.x;
    float s = 0.f;
    const int l0 = chunk * 128;
    for (int l = l0; l < l0 + 128; ++l)
        s += g_nodes[((size_t)b * LL + l) * HH + c];
    g_part[(b * 16 + chunk) * HH + c] = s;
}
__global__ void colmean_final()
{
    const int b = blockIdx.x, c = threadIdx.x;
    float s = 0.f;
    for (int t = 0; t < 16; ++t) s += g_part[(b * 16 + t) * HH + c];
    g_relay[b * HH + c] = s * (1.0f / (float)LL);
}

// ---------------- LayerNorm + concat relay -> fp16 --------------------------
__global__ void ln_concat_kernel(const float* __restrict__ gam, const float* __restrict__ bet)
{
    const int row = blockIdx.x;          // 0 .. B*2049-1
    const int b = row / LP1, l = row % LP1;
    const int tid = threadIdx.x;         // 128 threads, 4 floats each
    __half* oh = g_xy + (size_t)row * HH + tid * 4;

    float4 vv;
    if (l == LL) {
        vv = *(const float4*)(g_relay + b * HH + tid * 4);
        __half h[4];
        h[0] = __float2half_rn(vv.x); h[1] = __float2half_rn(vv.y);
        h[2] = __float2half_rn(vv.z); h[3] = __float2half_rn(vv.w);
        *(uint2*)oh = *(uint2*)h;
        return;
    }
    const float* x = g_nodes + ((size_t)b * LL + l) * HH;
    vv = *(const float4*)(x + tid * 4);
    float s  = vv.x + vv.y + vv.z + vv.w;
    float s2 = vv.x * vv.x + vv.y * vv.y + vv.z * vv.z + vv.w * vv.w;
    #pragma unroll
    for (int o = 16; o > 0; o >>= 1) {
        s  += __shfl_xor_sync(0xffffffffu, s,  o);
        s2 += __shfl_xor_sync(0xffffffffu, s2, o);
    }
    __shared__ float sh[8];
    const int wid = tid >> 5;
    if ((tid & 31) == 0) { sh[wid] = s; sh[4 + wid] = s2; }
    __syncthreads();
    const float S  = sh[0] + sh[1] + sh[2] + sh[3];
    const float S2 = sh[4] + sh[5] + sh[6] + sh[7];
    const float mu  = S * (1.0f / (float)HH);
    const float var = S2 * (1.0f / (float)HH) - mu * mu;
    const float inv = rsqrtf(var + 1e-6f);

    const float4 g4 = *(const float4*)(gam + tid * 4);
    const float4 b4 = *(const float4*)(bet + tid * 4);
    __half h[4];
    h[0] = __float2half_rn((vv.x - mu) * inv * g4.x + b4.x);
    h[1] = __float2half_rn((vv.y - mu) * inv * g4.y + b4.y);
    h[2] = __float2half_rn((vv.z - mu) * inv * g4.z + b4.z);
    h[3] = __float2half_rn((vv.w - mu) * inv * g4.w + b4.w);
    *(uint2*)oh = *(uint2*)h;
}

// -------------------- ring attention: 1 warp / (b,l,h) ----------------------
__global__ void ring_attn_kernel()
{
    const int lane = threadIdx.x & 31;
    const int gw = blockIdx.x * (blockDim.x >> 5) + (threadIdx.x >> 5);
    const int h = gw & 7;
    const int l = (gw >> 3) & (LL - 1);
    const int b = gw >> 14;

    const int qoff = (b * LP1 + l) * HH + h * HD;
    const float q0 = g_q[qoff + lane];
    const float q1 = g_q[qoff + 32 + lane];

    float s[4];
    int   koff[4];
    bool  ok[4];
    #pragma unroll
    for (int w = 0; w < 3; ++w) {
        const int lp = l - 1 + w;
        ok[w]   = (lp >= 0) && (lp < LL);
        koff[w] = (b * LP1 + lp) * HH + h * HD;
    }
    ok[3]   = true;
    koff[3] = (b * LP1 + LL) * HH + h * HD;

    #pragma unroll
    for (int w = 0; w < 4; ++w) {
        float p = 0.f;
        if (ok[w]) p = q0 * g_k[koff[w] + lane] + q1 * g_k[koff[w] + 32 + lane];
        s[w] = p;
    }
    #pragma unroll
    for (int o = 16; o > 0; o >>= 1) {
        #pragma unroll
        for (int w = 0; w < 4; ++w)
            s[w] += __shfl_xor_sync(0xffffffffu, s[w], o);
    }
    #pragma unroll
    for (int w = 0; w < 4; ++w) s[w] *= 0.125f;
    float m = fmaxf(fmaxf(s[0], s[1]), fmaxf(s[2], s[3]));
    float e[4], sum = 0.f;
    #pragma unroll
    for (int w = 0; w < 4; ++w) { e[w] = expf(s[w] - m); sum += e[w]; }
    const float inv = 1.0f / sum;

    float a0 = 0.f, a1 = 0.f;
    #pragma unroll
    for (int w = 0; w < 4; ++w) {
        if (ok[w]) {
            const float al = e[w] * inv;
            a0 += al * g_v[koff[w] + lane];
            a1 += al * g_v[koff[w] + 32 + lane];
        }
    }
    const int aoff = (b * LL + l) * HH + h * HD;
    g_att[aoff + lane]      = __float2half_rn(a0);
    g_att[aoff + 32 + lane] = __float2half_rn(a1);
}

// --------------- star attention: 1 block / (b,h), 256 thr -------------------
__global__ void star_attn_kernel()
{
    const int b = blockIdx.x >> 3, h = blockIdx.x & 7;
    const int tid = threadIdx.x;

    __shared__ float sc[LP1];
    __shared__ float qs[HD];
    __shared__ float red[8];
    __shared__ float part[4][HD];
    __shared__ float s_m, s_inv;

    const int qrow = (b * LP1 + LL) * HH + h * HD;
    if (tid < HD) qs[tid] = g_q[qrow + tid];
    __syncthreads();

    for (int j = tid; j < LP1; j += 256) {
        const float* kp = g_k + ((size_t)(b * LP1 + j)) * HH + h * HD;
        float s = 0.f;
        #pragma unroll
        for (int d = 0; d < HD; ++d) s += qs[d] * kp[d];
        sc[j] = s * 0.125f;
    }
    __syncthreads();

    float m = -3.4e38f;
    for (int j = tid; j < LP1; j += 256) m = fmaxf(m, sc[j]);
    #pragma unroll
    for (int o = 16; o > 0; o >>= 1) m = fmaxf(m, __shfl_xor_sync(0xffffffffu, m, o));
    if ((tid & 31) == 0) red[tid >> 5] = m;
    __syncthreads();
    if (tid == 0) {
        float mm = red[0];
        for (int w = 1; w < 8; ++w) mm = fmaxf(mm, red[w]);
        s_m = mm;
    }
    __syncthreads();
    m = s_m;

    float sum = 0.f;
    for (int j = tid; j < LP1; j += 256) {
        const float e = expf(sc[j] - m);
        sc[j] = e;
        sum += e;
    }
    #pragma unroll
    for (int o = 16; o > 0; o >>= 1) sum += __shfl_xor_sync(0xffffffffu, sum, o);
    __syncthreads();
    if ((tid & 31) == 0) red[tid >> 5] = sum;
    __syncthreads();
    if (tid == 0) {
        float ss = 0.f;
        for (int w = 0; w < 8; ++w) ss += red[w];
        s_inv = 1.0f / ss;
    }
    __syncthreads();
    const float inv = s_inv;

    const int g = tid >> 6, d = tid & 63;
    float acc = 0.f;
    for (int j = g; j < LP1; j += 4)
        acc += sc[j] * g_v[((size_t)(b * LP1 + j)) * HH + h * HD + d];
    part[g][d] = acc;
    __syncthreads();
    if (tid < HD) {
        const float r = (part[0][tid] + part[1][tid] + part[2][tid] + part[3][tid]) * inv;
        g_attr[b * HH + h * HD + tid] = r;
    }
}

// ------------------- star output projection (tiny GEMM) ---------------------
__global__ void star_out_kernel(const float* __restrict__ wo, const float* __restrict__ bo)
{
    const int b = blockIdx.x, c = threadIdx.x;
    __shared__ float a[HH];
    a[c] = g_attr[b * HH + c];
    __syncthreads();
    float s = bo[c];
    #pragma unroll 8
    for (int d = 0; d < HH; ++d) s += a[d] * wo[d * HH + c];
    g_relay[b * HH + c] = (s > 0.f) ? s : 0.2f * s;
}

// -------------------------- final: max + combine ----------------------------
__global__ void maxred_partial()
{
    const int b = blockIdx.x, chunk = blockIdx.y, c = threadIdx.x;
    float m = -3.4e38f;
    const int l0 = chunk * 128;
    for (int l = l0; l < l0 + 128; ++l)
        m = fmaxf(m, g_nodes[((size_t)b * LL + l) * HH + c]);
    g_part[(b * 16 + chunk) * HH + c] = m;
}
__global__ void final_out_kernel(float* __restrict__ out)
{
    const int b = blockIdx.x, c = threadIdx.x;
    float m = -3.4e38f;
    for (int t = 0; t < 16; ++t) m = fmaxf(m, g_part[(b * 16 + t) * HH + c]);
    out[b * HH + c] = 0.5f * (g_relay[b * HH + c] + m);
}

// ------------------------------- host driver --------------------------------
extern "C" void kernel_launch(void* const* d_in, const int* in_sizes, int n_in,
                              void* d_out, int out_size)
{
    const float* data    = (const float*)d_in[0];
    const float* fc_w    = (const float*)d_in[1];
    const float* fc_b    = (const float*)d_in[2];
    const float* pos_emb = (const float*)d_in[3];
    const float* ln_g    = (const float*)d_in[4];
    const float* ln_b    = (const float*)d_in[5];
    const float* wq      = (const float*)d_in[6];
    const float* wk      = (const float*)d_in[7];
    const float* wv      = (const float*)d_in[8];
    const float* bq      = (const float*)d_in[9];
    const float* bk      = (const float*)d_in[10];
    const float* bv      = (const float*)d_in[11];
    const float* ring_wo = (const float*)d_in[12];
    const float* ring_bo = (const float*)d_in[13];
    const float* star_wo = (const float*)d_in[14];
    const float* star_bo = (const float*)d_in[15];
    float* out = (float*)d_out;

    static bool attr_set = false;
    if (!attr_set) {
        cudaFuncSetAttribute(mma_gemm<0>, cudaFuncAttributeMaxDynamicSharedMemorySize, GEMM_SMEM);
        cudaFuncSetAttribute(mma_gemm<1>, cudaFuncAttributeMaxDynamicSharedMemorySize, GEMM_SMEM);
        cudaFuncSetAttribute(mma_gemm<2>, cudaFuncAttributeMaxDynamicSharedMemorySize, GEMM_SMEM);
        attr_set = true;
    }

    const int M_full = BB * LL;    // 16384
    const int M_xy   = BB * LP1;   // 16392
    const dim3 gFull(4, M_full / 128);              // (4,128)
    const dim3 gQKV (4, (M_xy + 127) / 128, 3);     // (4,129,3)

    // one-time per-call conversions (split keeps GEMM at launch #4)
    wconv_kernel<<<dim3(16, 16, NSLOT), dim3(32, 8)>>>(fc_w, wq, wk, wv, ring_wo);
    aconv_a_kernel<<<2048, 256>>>(data);
    aconv_b_kernel<<<2048, 256>>>(data);

    // embedding: nodes = data @ fc_w + fc_b + pos_emb      (launch #4)
    mma_gemm<0><<<gFull, 256, GEMM_SMEM>>>(0, M_full, fc_b, nullptr, nullptr, pos_emb);

    colmean_partial<<<dim3(BB, 16), HH>>>();
    colmean_final<<<BB, HH>>>();

    for (int i = 0; i < NL; ++i) {
        const int wOff = i * HH * HH;
        const int bOff = i * HH;

        ln_concat_kernel<<<M_xy, 128>>>(ln_g + bOff, ln_b + bOff);

        mma_gemm<1><<<gQKV, 256, GEMM_SMEM>>>(i, M_xy, bq + bOff, bk + bOff,
                                              bv + bOff, nullptr);

        ring_attn_kernel<<<(BB * LL * NHD) / 8, 256>>>();

        mma_gemm<2><<<gFull, 256, GEMM_SMEM>>>(i, M_full, ring_bo + bOff,
                                               nullptr, nullptr, nullptr);

        star_attn_kernel<<<BB * NHD, 256>>>();
        star_out_kernel<<<BB, HH>>>(star_wo + wOff, star_bo + bOff);
    }

    maxred_partial<<<dim3(BB, 16), HH>>>();
    final_out_kernel<<<BB, HH>>>(out);
}

// round 12
// speedup vs baseline: 1.1624x; 1.1624x over previous
#include <cuda_runtime.h>
#include <cuda_fp16.h>
#include <math.h>
#include <stdint.h>

// ---------------------------------------------------------------------------
// StarTransformer: B=8, L=2048, H=512, NH=8, HD=64, NUM_LAYERS=4
// GEMMs via mma.sync fp16 (HMMA) + ldmatrix, single-term fp16.
// R12: R10 GEMM config (best) + fp16 q/k/v + vectorized attention kernels.
// ---------------------------------------------------------------------------
#define BB   8
#define LL   2048
#define LP1  2049
#define HH   512
#define NHD  8
#define HD   64
#define NL   4
#define NSLOT 17        // fc_w + 4 layers x (wq,wk,wv,ring_wo)

// -------------------- scratch (device globals, no allocs) -------------------
__device__ float g_nodes[BB * LL * HH];
__device__ float g_relay[BB * HH];
__device__ float g_attr [BB * HH];
__device__ float g_part [BB * 16 * HH];

__device__ __half g_q   [BB * LP1 * HH];
__device__ __half g_k   [BB * LP1 * HH];
__device__ __half g_v   [BB * LP1 * HH];
__device__ __half g_data[BB * LL * HH];
__device__ __half g_xy  [BB * LP1 * HH];
__device__ __half g_att [BB * LL * HH];
__device__ __half g_wt  [NSLOT * HH * HH];   // W^T [n][k], fp16

// ------------------------------ helpers -------------------------------------
__device__ __forceinline__ uint32_t smem_u32(const void* p) {
    uint32_t a;
    asm("{ .reg .u64 t; cvta.to.shared.u64 t, %1; cvt.u32.u64 %0, t; }"
        : "=r"(a) : "l"(p));
    return a;
}
__device__ __forceinline__ void cp_async16(uint32_t dst, const void* src, uint32_t sz) {
    asm volatile("cp.async.cg.shared.global [%0], [%1], 16, %2;"
                 :: "r"(dst), "l"(src), "r"(sz));
}
#define CP_COMMIT() asm volatile("cp.async.commit_group;" ::: "memory")
#define CP_WAIT(n)  asm volatile("cp.async.wait_group %0;" :: "n"(n) : "memory")

__device__ __forceinline__ void ldsm_x4(uint32_t* r, uint32_t addr) {
    asm volatile("ldmatrix.sync.aligned.m8n8.x4.shared.b16 {%0,%1,%2,%3}, [%4];"
        : "=r"(r[0]), "=r"(r[1]), "=r"(r[2]), "=r"(r[3]) : "r"(addr));
}
__device__ __forceinline__ void mma16816(float* c, const uint32_t* a,
                                         uint32_t b0, uint32_t b1) {
    asm volatile(
        "mma.sync.aligned.m16n8k16.row.col.f32.f16.f16.f32 "
        "{%0,%1,%2,%3}, {%4,%5,%6,%7}, {%8,%9}, {%0,%1,%2,%3};"
        : "+f"(c[0]), "+f"(c[1]), "+f"(c[2]), "+f"(c[3])
        : "r"(a[0]), "r"(a[1]), "r"(a[2]), "r"(a[3]), "r"(b0), "r"(b1));
}

// ------------------------ mma.sync GEMM kernel ------------------------------
// D[M x 512] = A[M x 512] @ W_slot^T + epilogue.
// CTA tile 128m x 64n, BK=32. 8 warps as 2(m) x 4(n): warp tile 64m x 16n.
// 3-stage cp.async pipeline; ONE __syncthreads per k-iter. (R10 config)
// MODE 0: emb  (A = data, C = nodes f32, EPI: +bias +pos)
// MODE 1: qkv  (A = xy, blockIdx.z -> q/k/v fp16, EPI: +bias)
// MODE 2: ring (A = att, C = nodes f32, EPI: leaky_relu(+bias))
#define PADK 40                       // fp16 elems per smem row (32 + 8 pad)
#define A_SUB (128 * PADK * 2)        // 10240 B
#define B_SUB (64 * PADK * 2)         // 5120 B
#define STAGE_B (A_SUB + B_SUB)       // 15360 B
#define NSTAGE 3
#define GEMM_SMEM (NSTAGE * STAGE_B)  // 46080 B

template<int MODE>
__global__ __launch_bounds__(256, 3)
void mma_gemm(int layer, int M,
              const float* __restrict__ b0p, const float* __restrict__ b1p,
              const float* __restrict__ b2p, const float* __restrict__ pos)
{
    extern __shared__ __align__(128) char smem[];
    const uint32_t sb = smem_u32(smem);
    const int tid = threadIdx.x;
    const int lane = tid & 31, wid = tid >> 5;
    const int row0 = blockIdx.y * 128;
    const int col0 = blockIdx.x * 64;

    const __half* a_p;
    float* Cf = nullptr;
    __half* Ch = nullptr;
    const float* bias;
    int slot;
    if (MODE == 0) { a_p = g_data; Cf = g_nodes; bias = b0p; slot = 0; }
    else if (MODE == 1) {
        const int z = blockIdx.z;
        a_p = g_xy;
        Ch   = (z == 0) ? g_q : (z == 1) ? g_k : g_v;
        bias = (z == 0) ? b0p : (z == 1) ? b1p : b2p;
        slot = 1 + layer * 4 + z;
    } else { a_p = g_att; Cf = g_nodes; bias = b0p; slot = 1 + layer * 4 + 3; }
    const __half* w_p = g_wt + (size_t)slot * HH * HH;

    // ---- stage loader: 768 16B words (A 512, B 256) ----
    auto load_stage = [&](int stage, int kc) {
        const uint32_t stb = sb + stage * STAGE_B;
        #pragma unroll
        for (int it = 0; it < 3; ++it) {
            const int idx = it * 256 + tid;
            const int row = (idx & 511) >> 2;
            const int col = (idx & 3) * 8;
            uint32_t sz = 16;
            const __half* src;
            uint32_t doff;
            if (idx < 512) {           // A region
                const int gr = row0 + row;
                src = a_p + (size_t)gr * HH + kc + col;
                doff = 0u;
                if (gr >= M) { sz = 0; src = a_p; }
            } else {                   // B region (256 words, rows 0..63)
                src = w_p + (size_t)(col0 + row) * HH + kc + col;
                doff = A_SUB;
            }
            cp_async16(stb + doff + (uint32_t)(row * PADK + col) * 2, src, sz);
        }
        CP_COMMIT();
    };

    // warp tiling: 2(m) x 4(n)
    const int wm = (wid >> 2) * 64;     // 0 or 64
    const int wn = (wid & 3) * 16;      // 0,16,32,48

    // ldmatrix lane addressing
    const int lr = lane & 15;
    const int lc = (lane >> 4) * 8;

    float acc[4][2][4];
    #pragma unroll
    for (int mf = 0; mf < 4; ++mf)
        #pragma unroll
        for (int nf = 0; nf < 2; ++nf)
            #pragma unroll
            for (int e = 0; e < 4; ++e) acc[mf][nf][e] = 0.f;

    load_stage(0, 0);
    load_stage(1, 32);

    const int NT = HH / 32;   // 16
    for (int kt = 0; kt < NT; ++kt) {
        if (kt == NT - 1) { CP_WAIT(0); } else { CP_WAIT(1); }
        __syncthreads();

        if (kt + NSTAGE - 1 < NT)
            load_stage((kt + NSTAGE - 1) % NSTAGE, (kt + NSTAGE - 1) * 32);

        const uint32_t stb = sb + (kt % NSTAGE) * STAGE_B;
        const uint32_t sA = stb;
        const uint32_t sB = stb + A_SUB;

        #pragma unroll
        for (int ks = 0; ks < 2; ++ks) {
            const int k0 = ks * 16;
            uint32_t ah[4][4], bh[4];
            #pragma unroll
            for (int mf = 0; mf < 4; ++mf) {
                const uint32_t ro = (uint32_t)((wm + mf * 16 + lr) * PADK + k0 + lc) * 2;
                ldsm_x4(ah[mf], sA + ro);
            }
            {
                const uint32_t ro = (uint32_t)((wn + lr) * PADK + k0 + lc) * 2;
                ldsm_x4(bh, sB + ro);
            }
            #pragma unroll
            for (int mf = 0; mf < 4; ++mf) {
                mma16816(acc[mf][0], ah[mf], bh[0], bh[2]);
                mma16816(acc[mf][1], ah[mf], bh[1], bh[3]);
            }
        }
    }

    // epilogue
    #pragma unroll
    for (int mf = 0; mf < 4; ++mf) {
        const int rlo = row0 + wm + mf * 16 + (lane >> 2);
        #pragma unroll
        for (int nf = 0; nf < 2; ++nf) {
            const int c = col0 + wn + nf * 8 + (lane & 3) * 2;
            const float bx = bias[c], by = bias[c + 1];
            #pragma unroll
            for (int hrow = 0; hrow < 2; ++hrow) {
                const int r = rlo + hrow * 8;
                if (r >= M) continue;
                float vx = acc[mf][nf][hrow * 2 + 0] + bx;
                float vy = acc[mf][nf][hrow * 2 + 1] + by;
                if (MODE == 0) {
                    const size_t po = (size_t)(r & (LL - 1)) * HH + c;
                    vx += pos[po];
                    vy += pos[po + 1];
                }
                if (MODE == 2) {
                    vx = (vx > 0.f) ? vx : 0.2f * vx;
                    vy = (vy > 0.f) ? vy : 0.2f * vy;
                }
                if (MODE == 1) {
                    *(__half2*)(Ch + (size_t)r * HH + c) = __floats2half2_rn(vx, vy);
                } else {
                    *(float2*)(Cf + (size_t)r * HH + c) = make_float2(vx, vy);
                }
            }
        }
    }
}

// ------------------- weight transpose -> fp16 -------------------------------
__global__ void wconv_kernel(const float* __restrict__ fc_w, const float* __restrict__ wq,
                             const float* __restrict__ wk, const float* __restrict__ wv,
                             const float* __restrict__ ring_wo)
{
    const int z = blockIdx.z;
    const float* W;
    if (z == 0) W = fc_w;
    else {
        const int s = z - 1, layer = s >> 2, which = s & 3;
        const float* base = (which == 0) ? wq : (which == 1) ? wk
                          : (which == 2) ? wv : ring_wo;
        W = base + (size_t)layer * HH * HH;
    }
    __shared__ float t[32][33];
    const int x0 = blockIdx.x * 32, y0 = blockIdx.y * 32;
    const int tx = threadIdx.x, ty = threadIdx.y;   // (32,8)
    #pragma unroll
    for (int i = 0; i < 4; ++i)
        t[ty * 4 + i][tx] = W[(size_t)(y0 + ty * 4 + i) * HH + x0 + tx];
    __syncthreads();
    __half* wh = g_wt + (size_t)z * HH * HH;
    #pragma unroll
    for (int i = 0; i < 4; ++i) {
        const int n = x0 + ty * 4 + i, k = y0 + tx;
        wh[(size_t)n * HH + k] = __float2half_rn(t[tx][ty * 4 + i]);
    }
}

// ----------------------- data -> fp16 conversion (2 halves) -----------------
__global__ void aconv_a_kernel(const float* __restrict__ x)
{
    const int n4 = BB * LL * HH / 8;
    for (int i = blockIdx.x * blockDim.x + threadIdx.x; i < n4;
         i += gridDim.x * blockDim.x) {
        const float4 v = *(const float4*)(x + (size_t)i * 4);
        __half h[4];
        h[0] = __float2half_rn(v.x); h[1] = __float2half_rn(v.y);
        h[2] = __float2half_rn(v.z); h[3] = __float2half_rn(v.w);
        *(uint2*)(g_data + (size_t)i * 4) = *(uint2*)h;
    }
}
__global__ void aconv_b_kernel(const float* __restrict__ x)
{
    const int half = BB * LL * HH / 8;
    const int n4 = BB * LL * HH / 4;
    for (int i = half + blockIdx.x * blockDim.x + threadIdx.x; i < n4;
         i += gridDim.x * blockDim.x) {
        const float4 v = *(const float4*)(x + (size_t)i * 4);
        __half h[4];
        h[0] = __float2half_rn(v.x); h[1] = __float2half_rn(v.y);
        h[2] = __float2half_rn(v.z); h[3] = __float2half_rn(v.w);
        *(uint2*)(g_data + (size_t)i * 4) = *(uint2*)h;
    }
}

// ------------------------- relay init (column mean) -------------------------
__global__ void colmean_partial()
{
    const int b = blockIdx.x, chunk = blockIdx.y, c = threadIdx.x;
    float s = 0.f;
    const int l0 = chunk * 128;
    for (int l = l0; l < l0 + 128; ++l)
        s += g_nodes[((size_t)b * LL + l) * HH + c];
    g_part[(b * 16 + chunk) * HH + c] = s;
}
__global__ void colmean_final()
{
    const int b = blockIdx.x, c = threadIdx.x;
    float s = 0.f;
    for (int t = 0; t < 16; ++t) s += g_part[(b * 16 + t) * HH + c];
    g_relay[b * HH + c] = s * (1.0f / (float)LL);
}

// ---------------- LayerNorm + concat relay -> fp16 --------------------------
__global__ void ln_concat_kernel(const float* __restrict__ gam, const float* __restrict__ bet)
{
    const int row = blockIdx.x;          // 0 .. B*2049-1
    const int b = row / LP1, l = row % LP1;
    const int tid = threadIdx.x;         // 128 threads, 4 floats each
    __half* oh = g_xy + (size_t)row * HH + tid * 4;

    float4 vv;
    if (l == LL) {
        vv = *(const float4*)(g_relay + b * HH + tid * 4);
        __half h[4];
        h[0] = __float2half_rn(vv.x); h[1] = __float2half_rn(vv.y);
        h[2] = __float2half_rn(vv.z); h[3] = __float2half_rn(vv.w);
        *(uint2*)oh = *(uint2*)h;
        return;
    }
    const float* x = g_nodes + ((size_t)b * LL + l) * HH;
    vv = *(const float4*)(x + tid * 4);
    float s  = vv.x + vv.y + vv.z + vv.w;
    float s2 = vv.x * vv.x + vv.y * vv.y + vv.z * vv.z + vv.w * vv.w;
    #pragma unroll
    for (int o = 16; o > 0; o >>= 1) {
        s  += __shfl_xor_sync(0xffffffffu, s,  o);
        s2 += __shfl_xor_sync(0xffffffffu, s2, o);
    }
    __shared__ float sh[8];
    const int wid = tid >> 5;
    if ((tid & 31) == 0) { sh[wid] = s; sh[4 + wid] = s2; }
    __syncthreads();
    const float S  = sh[0] + sh[1] + sh[2] + sh[3];
    const float S2 = sh[4] + sh[5] + sh[6] + sh[7];
    const float mu  = S * (1.0f / (float)HH);
    const float var = S2 * (1.0f / (float)HH) - mu * mu;
    const float inv = rsqrtf(var + 1e-6f);

    const float4 g4 = *(const float4*)(gam + tid * 4);
    const float4 b4 = *(const float4*)(bet + tid * 4);
    __half h[4];
    h[0] = __float2half_rn((vv.x - mu) * inv * g4.x + b4.x);
    h[1] = __float2half_rn((vv.y - mu) * inv * g4.y + b4.y);
    h[2] = __float2half_rn((vv.z - mu) * inv * g4.z + b4.z);
    h[3] = __float2half_rn((vv.w - mu) * inv * g4.w + b4.w);
    *(uint2*)oh = *(uint2*)h;
}

// -------------------- ring attention: 1 warp / (b,l,h), fp16 ----------------
__global__ void ring_attn_kernel()
{
    const int lane = threadIdx.x & 31;
    const int gw = blockIdx.x * (blockDim.x >> 5) + (threadIdx.x >> 5);
    const int h = gw & 7;
    const int l = (gw >> 3) & (LL - 1);
    const int b = gw >> 14;

    const int qoff = (b * LP1 + l) * HH + h * HD;
    const __half2 q2 = *(const __half2*)(g_q + qoff + 2 * lane);
    const float q0 = __low2float(q2), q1 = __high2float(q2);

    float s[4];
    int   koff[4];
    bool  ok[4];
    #pragma unroll
    for (int w = 0; w < 3; ++w) {
        const int lp = l - 1 + w;
        ok[w]   = (lp >= 0) && (lp < LL);
        koff[w] = (b * LP1 + lp) * HH + h * HD;
    }
    ok[3]   = true;
    koff[3] = (b * LP1 + LL) * HH + h * HD;

    #pragma unroll
    for (int w = 0; w < 4; ++w) {
        float p = 0.f;
        if (ok[w]) {
            const __half2 k2 = *(const __half2*)(g_k + koff[w] + 2 * lane);
            p = q0 * __low2float(k2) + q1 * __high2float(k2);
        }
        s[w] = p;
    }
    #pragma unroll
    for (int o = 16; o > 0; o >>= 1) {
        #pragma unroll
        for (int w = 0; w < 4; ++w)
            s[w] += __shfl_xor_sync(0xffffffffu, s[w], o);
    }
    #pragma unroll
    for (int w = 0; w < 4; ++w) s[w] *= 0.125f;   // pad positions stay exactly 0
    float m = fmaxf(fmaxf(s[0], s[1]), fmaxf(s[2], s[3]));
    float e[4], sum = 0.f;
    #pragma unroll
    for (int w = 0; w < 4; ++w) { e[w] = expf(s[w] - m); sum += e[w]; }
    const float inv = 1.0f / sum;

    float a0 = 0.f, a1 = 0.f;
    #pragma unroll
    for (int w = 0; w < 4; ++w) {
        if (ok[w]) {
            const float al = e[w] * inv;
            const __half2 v2 = *(const __half2*)(g_v + koff[w] + 2 * lane);
            a0 += al * __low2float(v2);
            a1 += al * __high2float(v2);
        }
    }
    const int aoff = (b * LL + l) * HH + h * HD;
    *(__half2*)(g_att + aoff + 2 * lane) = __floats2half2_rn(a0, a1);
}

// --------------- star attention: 1 block / (b,h), 256 thr, fp16 -------------
__global__ void star_attn_kernel()
{
    const int b = blockIdx.x >> 3, h = blockIdx.x & 7;
    const int tid = threadIdx.x;

    __shared__ float sc[LP1];
    __shared__ float qs[HD];
    __shared__ float red[8];
    __shared__ float part[4][HD];
    __shared__ float s_m, s_inv;

    const int qrow = (b * LP1 + LL) * HH + h * HD;
    if (tid < HD) qs[tid] = __half2float(g_q[qrow + tid]);
    __syncthreads();

    for (int j = tid; j < LP1; j += 256) {
        const __half2* kp = (const __half2*)(g_k + ((size_t)(b * LP1 + j)) * HH + h * HD);
        float s = 0.f;
        #pragma unroll
        for (int d = 0; d < HD / 2; ++d) {
            const __half2 k2 = kp[d];
            s += qs[2 * d] * __low2float(k2) + qs[2 * d + 1] * __high2float(k2);
        }
        sc[j] = s * 0.125f;
    }
    __syncthreads();

    float m = -3.4e38f;
    for (int j = tid; j < LP1; j += 256) m = fmaxf(m, sc[j]);
    #pragma unroll
    for (int o = 16; o > 0; o >>= 1) m = fmaxf(m, __shfl_xor_sync(0xffffffffu, m, o));
    if ((tid & 31) == 0) red[tid >> 5] = m;
    __syncthreads();
    if (tid == 0) {
        float mm = red[0];
        for (int w = 1; w < 8; ++w) mm = fmaxf(mm, red[w]);
        s_m = mm;
    }
    __syncthreads();
    m = s_m;

    float sum = 0.f;
    for (int j = tid; j < LP1; j += 256) {
        const float e = expf(sc[j] - m);
        sc[j] = e;
        sum += e;
    }
    #pragma unroll
    for (int o = 16; o > 0; o >>= 1) sum += __shfl_xor_sync(0xffffffffu, sum, o);
    __syncthreads();
    if ((tid & 31) == 0) red[tid >> 5] = sum;
    __syncthreads();
    if (tid == 0) {
        float ss = 0.f;
        for (int w = 0; w < 8; ++w) ss += red[w];
        s_inv = 1.0f / ss;
    }
    __syncthreads();
    const float inv = s_inv;

    const int g = tid >> 6, d = tid & 63;
    float acc = 0.f;
    for (int j = g; j < LP1; j += 4)
        acc += sc[j] * __half2float(g_v[((size_t)(b * LP1 + j)) * HH + h * HD + d]);
    part[g][d] = acc;
    __syncthreads();
    if (tid < HD) {
        const float r = (part[0][tid] + part[1][tid] + part[2][tid] + part[3][tid]) * inv;
        g_attr[b * HH + h * HD + tid] = r;
    }
}

// ------------------- star output projection (tiny GEMM) ---------------------
__global__ void star_out_kernel(const float* __restrict__ wo, const float* __restrict__ bo)
{
    const int b = blockIdx.x, c = threadIdx.x;
    __shared__ float a[HH];
    a[c] = g_attr[b * HH + c];
    __syncthreads();
    float s = bo[c];
    #pragma unroll 8
    for (int d = 0; d < HH; ++d) s += a[d] * wo[d * HH + c];
    g_relay[b * HH + c] = (s > 0.f) ? s : 0.2f * s;
}

// -------------------------- final: max + combine ----------------------------
__global__ void maxred_partial()
{
    const int b = blockIdx.x, chunk = blockIdx.y, c = threadIdx.x;
    float m = -3.4e38f;
    const int l0 = chunk * 128;
    for (int l = l0; l < l0 + 128; ++l)
        m = fmaxf(m, g_nodes[((size_t)b * LL + l) * HH + c]);
    g_part[(b * 16 + chunk) * HH + c] = m;
}
__global__ void final_out_kernel(float* __restrict__ out)
{
    const int b = blockIdx.x, c = threadIdx.x;
    float m = -3.4e38f;
    for (int t = 0; t < 16; ++t) m = fmaxf(m, g_part[(b * 16 + t) * HH + c]);
    out[b * HH + c] = 0.5f * (g_relay[b * HH + c] + m);
}

// ------------------------------- host driver --------------------------------
extern "C" void kernel_launch(void* const* d_in, const int* in_sizes, int n_in,
                              void* d_out, int out_size)
{
    const float* data    = (const float*)d_in[0];
    const float* fc_w    = (const float*)d_in[1];
    const float* fc_b    = (const float*)d_in[2];
    const float* pos_emb = (const float*)d_in[3];
    const float* ln_g    = (const float*)d_in[4];
    const float* ln_b    = (const float*)d_in[5];
    const float* wq      = (const float*)d_in[6];
    const float* wk      = (const float*)d_in[7];
    const float* wv      = (const float*)d_in[8];
    const float* bq      = (const float*)d_in[9];
    const float* bk      = (const float*)d_in[10];
    const float* bv      = (const float*)d_in[11];
    const float* ring_wo = (const float*)d_in[12];
    const float* ring_bo = (const float*)d_in[13];
    const float* star_wo = (const float*)d_in[14];
    const float* star_bo = (const float*)d_in[15];
    float* out = (float*)d_out;

    static bool attr_set = false;
    if (!attr_set) {
        cudaFuncSetAttribute(mma_gemm<0>, cudaFuncAttributeMaxDynamicSharedMemorySize, GEMM_SMEM);
        cudaFuncSetAttribute(mma_gemm<1>, cudaFuncAttributeMaxDynamicSharedMemorySize, GEMM_SMEM);
        cudaFuncSetAttribute(mma_gemm<2>, cudaFuncAttributeMaxDynamicSharedMemorySize, GEMM_SMEM);
        attr_set = true;
    }

    const int M_full = BB * LL;    // 16384
    const int M_xy   = BB * LP1;   // 16392
    const dim3 gFull(8, M_full / 128);              // (8,128)
    const dim3 gQKV (8, (M_xy + 127) / 128, 3);     // (8,129,3)

    // one-time per-call conversions (split keeps GEMM at launch #4)
    wconv_kernel<<<dim3(16, 16, NSLOT), dim3(32, 8)>>>(fc_w, wq, wk, wv, ring_wo);
    aconv_a_kernel<<<2048, 256>>>(data);
    aconv_b_kernel<<<2048, 256>>>(data);

    // embedding: nodes = data @ fc_w + fc_b + pos_emb      (launch #4)
    mma_gemm<0><<<gFull, 256, GEMM_SMEM>>>(0, M_full, fc_b, nullptr, nullptr, pos_emb);

    colmean_partial<<<dim3(BB, 16), HH>>>();
    colmean_final<<<BB, HH>>>();

    for (int i = 0; i < NL; ++i) {
        const int wOff = i * HH * HH;
        const int bOff = i * HH;

        ln_concat_kernel<<<M_xy, 128>>>(ln_g + bOff, ln_b + bOff);

        mma_gemm<1><<<gQKV, 256, GEMM_SMEM>>>(i, M_xy, bq + bOff, bk + bOff,
                                              bv + bOff, nullptr);

        ring_attn_kernel<<<(BB * LL * NHD) / 8, 256>>>();

        mma_gemm<2><<<gFull, 256, GEMM_SMEM>>>(i, M_full, ring_bo + bOff,
                                               nullptr, nullptr, nullptr);

        star_attn_kernel<<<BB * NHD, 256>>>();
        star_out_kernel<<<BB, HH>>>(star_wo + wOff, star_bo + bOff);
    }

    maxred_partial<<<dim3(BB, 16), HH>>>();
    final_out_kernel<<<BB, HH>>>(out);
}

// round 13
// speedup vs baseline: 1.1829x; 1.0177x over previous
#include <cuda_runtime.h>
#include <cuda_fp16.h>
#include <math.h>
#include <stdint.h>

// ---------------------------------------------------------------------------
// StarTransformer: B=8, L=2048, H=512, NH=8, HD=64, NUM_LAYERS=4
// GEMMs via mma.sync fp16 (HMMA) + ldmatrix, single-term fp16.
// R13: warp layout 4m x 2n (32x32 warp tile) — 0.5 LDSM/MMA, A read 2x.
// ---------------------------------------------------------------------------
#define BB   8
#define LL   2048
#define LP1  2049
#define HH   512
#define NHD  8
#define HD   64
#define NL   4
#define NSLOT 17        // fc_w + 4 layers x (wq,wk,wv,ring_wo)

// -------------------- scratch (device globals, no allocs) -------------------
__device__ float g_nodes[BB * LL * HH];
__device__ float g_relay[BB * HH];
__device__ float g_attr [BB * HH];
__device__ float g_part [BB * 16 * HH];

__device__ __half g_q   [BB * LP1 * HH];
__device__ __half g_k   [BB * LP1 * HH];
__device__ __half g_v   [BB * LP1 * HH];
__device__ __half g_data[BB * LL * HH];
__device__ __half g_xy  [BB * LP1 * HH];
__device__ __half g_att [BB * LL * HH];
__device__ __half g_wt  [NSLOT * HH * HH];   // W^T [n][k], fp16

// ------------------------------ helpers -------------------------------------
__device__ __forceinline__ uint32_t smem_u32(const void* p) {
    uint32_t a;
    asm("{ .reg .u64 t; cvta.to.shared.u64 t, %1; cvt.u32.u64 %0, t; }"
        : "=r"(a) : "l"(p));
    return a;
}
__device__ __forceinline__ void cp_async16(uint32_t dst, const void* src, uint32_t sz) {
    asm volatile("cp.async.cg.shared.global [%0], [%1], 16, %2;"
                 :: "r"(dst), "l"(src), "r"(sz));
}
#define CP_COMMIT() asm volatile("cp.async.commit_group;" ::: "memory")
#define CP_WAIT(n)  asm volatile("cp.async.wait_group %0;" :: "n"(n) : "memory")

__device__ __forceinline__ void ldsm_x4(uint32_t* r, uint32_t addr) {
    asm volatile("ldmatrix.sync.aligned.m8n8.x4.shared.b16 {%0,%1,%2,%3}, [%4];"
        : "=r"(r[0]), "=r"(r[1]), "=r"(r[2]), "=r"(r[3]) : "r"(addr));
}
__device__ __forceinline__ void mma16816(float* c, const uint32_t* a,
                                         uint32_t b0, uint32_t b1) {
    asm volatile(
        "mma.sync.aligned.m16n8k16.row.col.f32.f16.f16.f32 "
        "{%0,%1,%2,%3}, {%4,%5,%6,%7}, {%8,%9}, {%0,%1,%2,%3};"
        : "+f"(c[0]), "+f"(c[1]), "+f"(c[2]), "+f"(c[3])
        : "r"(a[0]), "r"(a[1]), "r"(a[2]), "r"(a[3]), "r"(b0), "r"(b1));
}

// ------------------------ mma.sync GEMM kernel ------------------------------
// D[M x 512] = A[M x 512] @ W_slot^T + epilogue.
// CTA tile 128m x 64n, BK=32. 8 warps as 4(m) x 2(n): warp tile 32m x 32n.
// 3-stage cp.async pipeline; ONE __syncthreads per k-iter.
// MODE 0: emb  (A = data, C = nodes f32, EPI: +bias +pos)
// MODE 1: qkv  (A = xy, blockIdx.z -> q/k/v fp16, EPI: +bias)
// MODE 2: ring (A = att, C = nodes f32, EPI: leaky_relu(+bias))
#define PADK 40                       // fp16 elems per smem row (32 + 8 pad)
#define A_SUB (128 * PADK * 2)        // 10240 B
#define B_SUB (64 * PADK * 2)         // 5120 B
#define STAGE_B (A_SUB + B_SUB)       // 15360 B
#define NSTAGE 3
#define GEMM_SMEM (NSTAGE * STAGE_B)  // 46080 B

template<int MODE>
__global__ __launch_bounds__(256, 3)
void mma_gemm(int layer, int M,
              const float* __restrict__ b0p, const float* __restrict__ b1p,
              const float* __restrict__ b2p, const float* __restrict__ pos)
{
    extern __shared__ __align__(128) char smem[];
    const uint32_t sb = smem_u32(smem);
    const int tid = threadIdx.x;
    const int lane = tid & 31, wid = tid >> 5;
    const int row0 = blockIdx.y * 128;
    const int col0 = blockIdx.x * 64;

    const __half* a_p;
    float* Cf = nullptr;
    __half* Ch = nullptr;
    const float* bias;
    int slot;
    if (MODE == 0) { a_p = g_data; Cf = g_nodes; bias = b0p; slot = 0; }
    else if (MODE == 1) {
        const int z = blockIdx.z;
        a_p = g_xy;
        Ch   = (z == 0) ? g_q : (z == 1) ? g_k : g_v;
        bias = (z == 0) ? b0p : (z == 1) ? b1p : b2p;
        slot = 1 + layer * 4 + z;
    } else { a_p = g_att; Cf = g_nodes; bias = b0p; slot = 1 + layer * 4 + 3; }
    const __half* w_p = g_wt + (size_t)slot * HH * HH;

    // ---- stage loader: 768 16B words (A 512, B 256) ----
    auto load_stage = [&](int stage, int kc) {
        const uint32_t stb = sb + stage * STAGE_B;
        #pragma unroll
        for (int it = 0; it < 3; ++it) {
            const int idx = it * 256 + tid;
            const int row = (idx & 511) >> 2;
            const int col = (idx & 3) * 8;
            uint32_t sz = 16;
            const __half* src;
            uint32_t doff;
            if (idx < 512) {           // A region
                const int gr = row0 + row;
                src = a_p + (size_t)gr * HH + kc + col;
                doff = 0u;
                if (gr >= M) { sz = 0; src = a_p; }
            } else {                   // B region (256 words, rows 0..63)
                src = w_p + (size_t)(col0 + row) * HH + kc + col;
                doff = A_SUB;
            }
            cp_async16(stb + doff + (uint32_t)(row * PADK + col) * 2, src, sz);
        }
        CP_COMMIT();
    };

    // warp tiling: 4(m) x 2(n)
    const int wm = (wid >> 1) * 32;     // 0,32,64,96
    const int wn = (wid & 1) * 32;      // 0,32

    // ldmatrix lane addressing
    const int lr = lane & 15;
    const int lc = (lane >> 4) * 8;

    float acc[2][4][4];
    #pragma unroll
    for (int mf = 0; mf < 2; ++mf)
        #pragma unroll
        for (int nf = 0; nf < 4; ++nf)
            #pragma unroll
            for (int e = 0; e < 4; ++e) acc[mf][nf][e] = 0.f;

    load_stage(0, 0);
    load_stage(1, 32);

    const int NT = HH / 32;   // 16
    for (int kt = 0; kt < NT; ++kt) {
        if (kt == NT - 1) { CP_WAIT(0); } else { CP_WAIT(1); }
        __syncthreads();

        if (kt + NSTAGE - 1 < NT)
            load_stage((kt + NSTAGE - 1) % NSTAGE, (kt + NSTAGE - 1) * 32);

        const uint32_t stb = sb + (kt % NSTAGE) * STAGE_B;
        const uint32_t sA = stb;
        const uint32_t sB = stb + A_SUB;

        #pragma unroll
        for (int ks = 0; ks < 2; ++ks) {
            const int k0 = ks * 16;
            uint32_t ah[2][4];
            #pragma unroll
            for (int mf = 0; mf < 2; ++mf) {
                const uint32_t ro = (uint32_t)((wm + mf * 16 + lr) * PADK + k0 + lc) * 2;
                ldsm_x4(ah[mf], sA + ro);
            }
            #pragma unroll
            for (int p = 0; p < 2; ++p) {
                uint32_t bh[4];
                const uint32_t ro = (uint32_t)((wn + p * 16 + lr) * PADK + k0 + lc) * 2;
                ldsm_x4(bh, sB + ro);
                const int nf0 = p * 2, nf1 = p * 2 + 1;
                #pragma unroll
                for (int mf = 0; mf < 2; ++mf) {
                    mma16816(acc[mf][nf0], ah[mf], bh[0], bh[2]);
                    mma16816(acc[mf][nf1], ah[mf], bh[1], bh[3]);
                }
            }
        }
    }

    // epilogue
    #pragma unroll
    for (int mf = 0; mf < 2; ++mf) {
        const int rlo = row0 + wm + mf * 16 + (lane >> 2);
        #pragma unroll
        for (int nf = 0; nf < 4; ++nf) {
            const int c = col0 + wn + nf * 8 + (lane & 3) * 2;
            const float bx = bias[c], by = bias[c + 1];
            #pragma unroll
            for (int hrow = 0; hrow < 2; ++hrow) {
                const int r = rlo + hrow * 8;
                if (r >= M) continue;
                float vx = acc[mf][nf][hrow * 2 + 0] + bx;
                float vy = acc[mf][nf][hrow * 2 + 1] + by;
                if (MODE == 0) {
                    const size_t po = (size_t)(r & (LL - 1)) * HH + c;
                    vx += pos[po];
                    vy += pos[po + 1];
                }
                if (MODE == 2) {
                    vx = (vx > 0.f) ? vx : 0.2f * vx;
                    vy = (vy > 0.f) ? vy : 0.2f * vy;
                }
                if (MODE == 1) {
                    *(__half2*)(Ch + (size_t)r * HH + c) = __floats2half2_rn(vx, vy);
                } else {
                    *(float2*)(Cf + (size_t)r * HH + c) = make_float2(vx, vy);
                }
            }
        }
    }
}

// ------------------- weight transpose -> fp16 -------------------------------
__global__ void wconv_kernel(const float* __restrict__ fc_w, const float* __restrict__ wq,
                             const float* __restrict__ wk, const float* __restrict__ wv,
                             const float* __restrict__ ring_wo)
{
    const int z = blockIdx.z;
    const float* W;
    if (z == 0) W = fc_w;
    else {
        const int s = z - 1, layer = s >> 2, which = s & 3;
        const float* base = (which == 0) ? wq : (which == 1) ? wk
                          : (which == 2) ? wv : ring_wo;
        W = base + (size_t)layer * HH * HH;
    }
    __shared__ float t[32][33];
    const int x0 = blockIdx.x * 32, y0 = blockIdx.y * 32;
    const int tx = threadIdx.x, ty = threadIdx.y;   // (32,8)
    #pragma unroll
    for (int i = 0; i < 4; ++i)
        t[ty * 4 + i][tx] = W[(size_t)(y0 + ty * 4 + i) * HH + x0 + tx];
    __syncthreads();
    __half* wh = g_wt + (size_t)z * HH * HH;
    #pragma unroll
    for (int i = 0; i < 4; ++i) {
        const int n = x0 + ty * 4 + i, k = y0 + tx;
        wh[(size_t)n * HH + k] = __float2half_rn(t[tx][ty * 4 + i]);
    }
}

// ----------------------- data -> fp16 conversion (2 halves) -----------------
__global__ void aconv_a_kernel(const float* __restrict__ x)
{
    const int n4 = BB * LL * HH / 8;
    for (int i = blockIdx.x * blockDim.x + threadIdx.x; i < n4;
         i += gridDim.x * blockDim.x) {
        const float4 v = *(const float4*)(x + (size_t)i * 4);
        __half h[4];
        h[0] = __float2half_rn(v.x); h[1] = __float2half_rn(v.y);
        h[2] = __float2half_rn(v.z); h[3] = __float2half_rn(v.w);
        *(uint2*)(g_data + (size_t)i * 4) = *(uint2*)h;
    }
}
__global__ void aconv_b_kernel(const float* __restrict__ x)
{
    const int half = BB * LL * HH / 8;
    const int n4 = BB * LL * HH / 4;
    for (int i = half + blockIdx.x * blockDim.x + threadIdx.x; i < n4;
         i += gridDim.x * blockDim.x) {
        const float4 v = *(const float4*)(x + (size_t)i * 4);
        __half h[4];
        h[0] = __float2half_rn(v.x); h[1] = __float2half_rn(v.y);
        h[2] = __float2half_rn(v.z); h[3] = __float2half_rn(v.w);
        *(uint2*)(g_data + (size_t)i * 4) = *(uint2*)h;
    }
}

// ------------------------- relay init (column mean) -------------------------
__global__ void colmean_partial()
{
    const int b = blockIdx.x, chunk = blockIdx.y, c = threadIdx.x;
    float s = 0.f;
    const int l0 = chunk * 128;
    for (int l = l0; l < l0 + 128; ++l)
        s += g_nodes[((size_t)b * LL + l) * HH + c];
    g_part[(b * 16 + chunk) * HH + c] = s;
}
__global__ void colmean_final()
{
    const int b = blockIdx.x, c = threadIdx.x;
    float s = 0.f;
    for (int t = 0; t < 16; ++t) s += g_part[(b * 16 + t) * HH + c];
    g_relay[b * HH + c] = s * (1.0f / (float)LL);
}

// ---------------- LayerNorm + concat relay -> fp16 --------------------------
__global__ void ln_concat_kernel(const float* __restrict__ gam, const float* __restrict__ bet)
{
    const int row = blockIdx.x;          // 0 .. B*2049-1
    const int b = row / LP1, l = row % LP1;
    const int tid = threadIdx.x;         // 128 threads, 4 floats each
    __half* oh = g_xy + (size_t)row * HH + tid * 4;

    float4 vv;
    if (l == LL) {
        vv = *(const float4*)(g_relay + b * HH + tid * 4);
        __half h[4];
        h[0] = __float2half_rn(vv.x); h[1] = __float2half_rn(vv.y);
        h[2] = __float2half_rn(vv.z); h[3] = __float2half_rn(vv.w);
        *(uint2*)oh = *(uint2*)h;
        return;
    }
    const float* x = g_nodes + ((size_t)b * LL + l) * HH;
    vv = *(const float4*)(x + tid * 4);
    float s  = vv.x + vv.y + vv.z + vv.w;
    float s2 = vv.x * vv.x + vv.y * vv.y + vv.z * vv.z + vv.w * vv.w;
    #pragma unroll
    for (int o = 16; o > 0; o >>= 1) {
        s  += __shfl_xor_sync(0xffffffffu, s,  o);
        s2 += __shfl_xor_sync(0xffffffffu, s2, o);
    }
    __shared__ float sh[8];
    const int wid = tid >> 5;
    if ((tid & 31) == 0) { sh[wid] = s; sh[4 + wid] = s2; }
    __syncthreads();
    const float S  = sh[0] + sh[1] + sh[2] + sh[3];
    const float S2 = sh[4] + sh[5] + sh[6] + sh[7];
    const float mu  = S * (1.0f / (float)HH);
    const float var = S2 * (1.0f / (float)HH) - mu * mu;
    const float inv = rsqrtf(var + 1e-6f);

    const float4 g4 = *(const float4*)(gam + tid * 4);
    const float4 b4 = *(const float4*)(bet + tid * 4);
    __half h[4];
    h[0] = __float2half_rn((vv.x - mu) * inv * g4.x + b4.x);
    h[1] = __float2half_rn((vv.y - mu) * inv * g4.y + b4.y);
    h[2] = __float2half_rn((vv.z - mu) * inv * g4.z + b4.z);
    h[3] = __float2half_rn((vv.w - mu) * inv * g4.w + b4.w);
    *(uint2*)oh = *(uint2*)h;
}

// -------------------- ring attention: 1 warp / (b,l,h), fp16 ----------------
__global__ void ring_attn_kernel()
{
    const int lane = threadIdx.x & 31;
    const int gw = blockIdx.x * (blockDim.x >> 5) + (threadIdx.x >> 5);
    const int h = gw & 7;
    const int l = (gw >> 3) & (LL - 1);
    const int b = gw >> 14;

    const int qoff = (b * LP1 + l) * HH + h * HD;
    const __half2 q2 = *(const __half2*)(g_q + qoff + 2 * lane);
    const float q0 = __low2float(q2), q1 = __high2float(q2);

    float s[4];
    int   koff[4];
    bool  ok[4];
    #pragma unroll
    for (int w = 0; w < 3; ++w) {
        const int lp = l - 1 + w;
        ok[w]   = (lp >= 0) && (lp < LL);
        koff[w] = (b * LP1 + lp) * HH + h * HD;
    }
    ok[3]   = true;
    koff[3] = (b * LP1 + LL) * HH + h * HD;

    #pragma unroll
    for (int w = 0; w < 4; ++w) {
        float p = 0.f;
        if (ok[w]) {
            const __half2 k2 = *(const __half2*)(g_k + koff[w] + 2 * lane);
            p = q0 * __low2float(k2) + q1 * __high2float(k2);
        }
        s[w] = p;
    }
    #pragma unroll
    for (int o = 16; o > 0; o >>= 1) {
        #pragma unroll
        for (int w = 0; w < 4; ++w)
            s[w] += __shfl_xor_sync(0xffffffffu, s[w], o);
    }
    #pragma unroll
    for (int w = 0; w < 4; ++w) s[w] *= 0.125f;   // pad positions stay exactly 0
    float m = fmaxf(fmaxf(s[0], s[1]), fmaxf(s[2], s[3]));
    float e[4], sum = 0.f;
    #pragma unroll
    for (int w = 0; w < 4; ++w) { e[w] = expf(s[w] - m); sum += e[w]; }
    const float inv = 1.0f / sum;

    float a0 = 0.f, a1 = 0.f;
    #pragma unroll
    for (int w = 0; w < 4; ++w) {
        if (ok[w]) {
            const float al = e[w] * inv;
            const __half2 v2 = *(const __half2*)(g_v + koff[w] + 2 * lane);
            a0 += al * __low2float(v2);
            a1 += al * __high2float(v2);
        }
    }
    const int aoff = (b * LL + l) * HH + h * HD;
    *(__half2*)(g_att + aoff + 2 * lane) = __floats2half2_rn(a0, a1);
}

// --------------- star attention: 1 block / (b,h), 256 thr, fp16 -------------
__global__ void star_attn_kernel()
{
    const int b = blockIdx.x >> 3, h = blockIdx.x & 7;
    const int tid = threadIdx.x;

    __shared__ float sc[LP1];
    __shared__ float qs[HD];
    __shared__ float red[8];
    __shared__ float part[4][HD];
    __shared__ float s_m, s_inv;

    const int qrow = (b * LP1 + LL) * HH + h * HD;
    if (tid < HD) qs[tid] = __half2float(g_q[qrow + tid]);
    __syncthreads();

    for (int j = tid; j < LP1; j += 256) {
        const __half2* kp = (const __half2*)(g_k + ((size_t)(b * LP1 + j)) * HH + h * HD);
        float s = 0.f;
        #pragma unroll
        for (int d = 0; d < HD / 2; ++d) {
            const __half2 k2 = kp[d];
            s += qs[2 * d] * __low2float(k2) + qs[2 * d + 1] * __high2float(k2);
        }
        sc[j] = s * 0.125f;
    }
    __syncthreads();

    float m = -3.4e38f;
    for (int j = tid; j < LP1; j += 256) m = fmaxf(m, sc[j]);
    #pragma unroll
    for (int o = 16; o > 0; o >>= 1) m = fmaxf(m, __shfl_xor_sync(0xffffffffu, m, o));
    if ((tid & 31) == 0) red[tid >> 5] = m;
    __syncthreads();
    if (tid == 0) {
        float mm = red[0];
        for (int w = 1; w < 8; ++w) mm = fmaxf(mm, red[w]);
        s_m = mm;
    }
    __syncthreads();
    m = s_m;

    float sum = 0.f;
    for (int j = tid; j < LP1; j += 256) {
        const float e = expf(sc[j] - m);
        sc[j] = e;
        sum += e;
    }
    #pragma unroll
    for (int o = 16; o > 0; o >>= 1) sum += __shfl_xor_sync(0xffffffffu, sum, o);
    __syncthreads();
    if ((tid & 31) == 0) red[tid >> 5] = sum;
    __syncthreads();
    if (tid == 0) {
        float ss = 0.f;
        for (int w = 0; w < 8; ++w) ss += red[w];
        s_inv = 1.0f / ss;
    }
    __syncthreads();
    const float inv = s_inv;

    const int g = tid >> 6, d = tid & 63;
    float acc = 0.f;
    for (int j = g; j < LP1; j += 4)
        acc += sc[j] * __half2float(g_v[((size_t)(b * LP1 + j)) * HH + h * HD + d]);
    part[g][d] = acc;
    __syncthreads();
    if (tid < HD) {
        const float r = (part[0][tid] + part[1][tid] + part[2][tid] + part[3][tid]) * inv;
        g_attr[b * HH + h * HD + tid] = r;
    }
}

// ------------------- star output projection (tiny GEMM) ---------------------
__global__ void star_out_kernel(const float* __restrict__ wo, const float* __restrict__ bo)
{
    const int b = blockIdx.x, c = threadIdx.x;
    __shared__ float a[HH];
    a[c] = g_attr[b * HH + c];
    __syncthreads();
    float s = bo[c];
    #pragma unroll 8
    for (int d = 0; d < HH; ++d) s += a[d] * wo[d * HH + c];
    g_relay[b * HH + c] = (s > 0.f) ? s : 0.2f * s;
}

// -------------------------- final: max + combine ----------------------------
__global__ void maxred_partial()
{
    const int b = blockIdx.x, chunk = blockIdx.y, c = threadIdx.x;
    float m = -3.4e38f;
    const int l0 = chunk * 128;
    for (int l = l0; l < l0 + 128; ++l)
        m = fmaxf(m, g_nodes[((size_t)b * LL + l) * HH + c]);
    g_part[(b * 16 + chunk) * HH + c] = m;
}
__global__ void final_out_kernel(float* __restrict__ out)
{
    const int b = blockIdx.x, c = threadIdx.x;
    float m = -3.4e38f;
    for (int t = 0; t < 16; ++t) m = fmaxf(m, g_part[(b * 16 + t) * HH + c]);
    out[b * HH + c] = 0.5f * (g_relay[b * HH + c] + m);
}

// ------------------------------- host driver --------------------------------
extern "C" void kernel_launch(void* const* d_in, const int* in_sizes, int n_in,
                              void* d_out, int out_size)
{
    const float* data    = (const float*)d_in[0];
    const float* fc_w    = (const float*)d_in[1];
    const float* fc_b    = (const float*)d_in[2];
    const float* pos_emb = (const float*)d_in[3];
    const float* ln_g    = (const float*)d_in[4];
    const float* ln_b    = (const float*)d_in[5];
    const float* wq      = (const float*)d_in[6];
    const float* wk      = (const float*)d_in[7];
    const float* wv      = (const float*)d_in[8];
    const float* bq      = (const float*)d_in[9];
    const float* bk      = (const float*)d_in[10];
    const float* bv      = (const float*)d_in[11];
    const float* ring_wo = (const float*)d_in[12];
    const float* ring_bo = (const float*)d_in[13];
    const float* star_wo = (const float*)d_in[14];
    const float* star_bo = (const float*)d_in[15];
    float* out = (float*)d_out;

    static bool attr_set = false;
    if (!attr_set) {
        cudaFuncSetAttribute(mma_gemm<0>, cudaFuncAttributeMaxDynamicSharedMemorySize, GEMM_SMEM);
        cudaFuncSetAttribute(mma_gemm<1>, cudaFuncAttributeMaxDynamicSharedMemorySize, GEMM_SMEM);
        cudaFuncSetAttribute(mma_gemm<2>, cudaFuncAttributeMaxDynamicSharedMemorySize, GEMM_SMEM);
        attr_set = true;
    }

    const int M_full = BB * LL;    // 16384
    const int M_xy   = BB * LP1;   // 16392
    const dim3 gFull(8, M_full / 128);              // (8,128)
    const dim3 gQKV (8, (M_xy + 127) / 128, 3);     // (8,129,3)

    // one-time per-call conversions (split keeps GEMM at launch #4)
    wconv_kernel<<<dim3(16, 16, NSLOT), dim3(32, 8)>>>(fc_w, wq, wk, wv, ring_wo);
    aconv_a_kernel<<<2048, 256>>>(data);
    aconv_b_kernel<<<2048, 256>>>(data);

    // embedding: nodes = data @ fc_w + fc_b + pos_emb      (launch #4)
    mma_gemm<0><<<gFull, 256, GEMM_SMEM>>>(0, M_full, fc_b, nullptr, nullptr, pos_emb);

    colmean_partial<<<dim3(BB, 16), HH>>>();
    colmean_final<<<BB, HH>>>();

    for (int i = 0; i < NL; ++i) {
        const int wOff = i * HH * HH;
        const int bOff = i * HH;

        ln_concat_kernel<<<M_xy, 128>>>(ln_g + bOff, ln_b + bOff);

        mma_gemm<1><<<gQKV, 256, GEMM_SMEM>>>(i, M_xy, bq + bOff, bk + bOff,
                                              bv + bOff, nullptr);

        ring_attn_kernel<<<(BB * LL * NHD) / 8, 256>>>();

        mma_gemm<2><<<gFull, 256, GEMM_SMEM>>>(i, M_full, ring_bo + bOff,
                                               nullptr, nullptr, nullptr);

        star_attn_kernel<<<BB * NHD, 256>>>();
        star_out_kernel<<<BB, HH>>>(star_wo + wOff, star_bo + bOff);
    }

    maxred_partial<<<dim3(BB, 16), HH>>>();
    final_out_kernel<<<BB, HH>>>(out);
}

// round 15
// speedup vs baseline: 1.5191x; 1.2842x over previous
#include <cuda_runtime.h>
#include <cuda_fp16.h>
#include <math.h>
#include <stdint.h>

// ---------------------------------------------------------------------------
// StarTransformer: B=8, L=2048, H=512, NH=8, HD=64, NUM_LAYERS=4
// GEMMs via mma.sync fp16 (HMMA) + ldmatrix, single-term fp16.
// R15: R13 kernels + two-stream fork/join (star branch overlaps ring branch).
// ---------------------------------------------------------------------------
#define BB   8
#define LL   2048
#define LP1  2049
#define HH   512
#define NHD  8
#define HD   64
#define NL   4
#define NSLOT 17        // fc_w + 4 layers x (wq,wk,wv,ring_wo)

// -------------------- scratch (device globals, no allocs) -------------------
__device__ float g_nodes[BB * LL * HH];
__device__ float g_relay[BB * HH];
__device__ float g_attr [BB * HH];
__device__ float g_part [BB * 16 * HH];

__device__ __half g_q   [BB * LP1 * HH];
__device__ __half g_k   [BB * LP1 * HH];
__device__ __half g_v   [BB * LP1 * HH];
__device__ __half g_data[BB * LL * HH];
__device__ __half g_xy  [BB * LP1 * HH];
__device__ __half g_att [BB * LL * HH];
__device__ __half g_wt  [NSLOT * HH * HH];   // W^T [n][k], fp16

// ------------------------------ helpers -------------------------------------
__device__ __forceinline__ uint32_t smem_u32(const void* p) {
    uint32_t a;
    asm("{ .reg .u64 t; cvta.to.shared.u64 t, %1; cvt.u32.u64 %0, t; }"
        : "=r"(a) : "l"(p));
    return a;
}
__device__ __forceinline__ void cp_async16(uint32_t dst, const void* src, uint32_t sz) {
    asm volatile("cp.async.cg.shared.global [%0], [%1], 16, %2;"
                 :: "r"(dst), "l"(src), "r"(sz));
}
#define CP_COMMIT() asm volatile("cp.async.commit_group;" ::: "memory")
#define CP_WAIT(n)  asm volatile("cp.async.wait_group %0;" :: "n"(n) : "memory")

__device__ __forceinline__ void ldsm_x4(uint32_t* r, uint32_t addr) {
    asm volatile("ldmatrix.sync.aligned.m8n8.x4.shared.b16 {%0,%1,%2,%3}, [%4];"
        : "=r"(r[0]), "=r"(r[1]), "=r"(r[2]), "=r"(r[3]) : "r"(addr));
}
__device__ __forceinline__ void mma16816(float* c, const uint32_t* a,
                                         uint32_t b0, uint32_t b1) {
    asm volatile(
        "mma.sync.aligned.m16n8k16.row.col.f32.f16.f16.f32 "
        "{%0,%1,%2,%3}, {%4,%5,%6,%7}, {%8,%9}, {%0,%1,%2,%3};"
        : "+f"(c[0]), "+f"(c[1]), "+f"(c[2]), "+f"(c[3])
        : "r"(a[0]), "r"(a[1]), "r"(a[2]), "r"(a[3]), "r"(b0), "r"(b1));
}

// ------------------------ mma.sync GEMM kernel ------------------------------
// CTA tile 128m x 64n, BK=32. 8 warps as 4(m) x 2(n): warp tile 32m x 32n.
// 3-stage cp.async pipeline; ONE __syncthreads per k-iter. (R13 config)
#define PADK 40                       // fp16 elems per smem row (32 + 8 pad)
#define A_SUB (128 * PADK * 2)        // 10240 B
#define B_SUB (64 * PADK * 2)         // 5120 B
#define STAGE_B (A_SUB + B_SUB)       // 15360 B
#define NSTAGE 3
#define GEMM_SMEM (NSTAGE * STAGE_B)  // 46080 B

template<int MODE>
__global__ __launch_bounds__(256, 3)
void mma_gemm(int layer, int M,
              const float* __restrict__ b0p, const float* __restrict__ b1p,
              const float* __restrict__ b2p, const float* __restrict__ pos)
{
    extern __shared__ __align__(128) char smem[];
    const uint32_t sb = smem_u32(smem);
    const int tid = threadIdx.x;
    const int lane = tid & 31, wid = tid >> 5;
    const int row0 = blockIdx.y * 128;
    const int col0 = blockIdx.x * 64;

    const __half* a_p;
    float* Cf = nullptr;
    __half* Ch = nullptr;
    const float* bias;
    int slot;
    if (MODE == 0) { a_p = g_data; Cf = g_nodes; bias = b0p; slot = 0; }
    else if (MODE == 1) {
        const int z = blockIdx.z;
        a_p = g_xy;
        Ch   = (z == 0) ? g_q : (z == 1) ? g_k : g_v;
        bias = (z == 0) ? b0p : (z == 1) ? b1p : b2p;
        slot = 1 + layer * 4 + z;
    } else { a_p = g_att; Cf = g_nodes; bias = b0p; slot = 1 + layer * 4 + 3; }
    const __half* w_p = g_wt + (size_t)slot * HH * HH;

    auto load_stage = [&](int stage, int kc) {
        const uint32_t stb = sb + stage * STAGE_B;
        #pragma unroll
        for (int it = 0; it < 3; ++it) {
            const int idx = it * 256 + tid;
            const int row = (idx & 511) >> 2;
            const int col = (idx & 3) * 8;
            uint32_t sz = 16;
            const __half* src;
            uint32_t doff;
            if (idx < 512) {           // A region
                const int gr = row0 + row;
                src = a_p + (size_t)gr * HH + kc + col;
                doff = 0u;
                if (gr >= M) { sz = 0; src = a_p; }
            } else {                   // B region (256 words, rows 0..63)
                src = w_p + (size_t)(col0 + row) * HH + kc + col;
                doff = A_SUB;
            }
            cp_async16(stb + doff + (uint32_t)(row * PADK + col) * 2, src, sz);
        }
        CP_COMMIT();
    };

    // warp tiling: 4(m) x 2(n)
    const int wm = (wid >> 1) * 32;     // 0,32,64,96
    const int wn = (wid & 1) * 32;      // 0,32

    const int lr = lane & 15;
    const int lc = (lane >> 4) * 8;

    float acc[2][4][4];
    #pragma unroll
    for (int mf = 0; mf < 2; ++mf)
        #pragma unroll
        for (int nf = 0; nf < 4; ++nf)
            #pragma unroll
            for (int e = 0; e < 4; ++e) acc[mf][nf][e] = 0.f;

    load_stage(0, 0);
    load_stage(1, 32);

    const int NT = HH / 32;   // 16
    for (int kt = 0; kt < NT; ++kt) {
        if (kt == NT - 1) { CP_WAIT(0); } else { CP_WAIT(1); }
        __syncthreads();

        if (kt + NSTAGE - 1 < NT)
            load_stage((kt + NSTAGE - 1) % NSTAGE, (kt + NSTAGE - 1) * 32);

        const uint32_t stb = sb + (kt % NSTAGE) * STAGE_B;
        const uint32_t sA = stb;
        const uint32_t sB = stb + A_SUB;

        #pragma unroll
        for (int ks = 0; ks < 2; ++ks) {
            const int k0 = ks * 16;
            uint32_t ah[2][4];
            #pragma unroll
            for (int mf = 0; mf < 2; ++mf) {
                const uint32_t ro = (uint32_t)((wm + mf * 16 + lr) * PADK + k0 + lc) * 2;
                ldsm_x4(ah[mf], sA + ro);
            }
            #pragma unroll
            for (int p = 0; p < 2; ++p) {
                uint32_t bh[4];
                const uint32_t ro = (uint32_t)((wn + p * 16 + lr) * PADK + k0 + lc) * 2;
                ldsm_x4(bh, sB + ro);
                const int nf0 = p * 2, nf1 = p * 2 + 1;
                #pragma unroll
                for (int mf = 0; mf < 2; ++mf) {
                    mma16816(acc[mf][nf0], ah[mf], bh[0], bh[2]);
                    mma16816(acc[mf][nf1], ah[mf], bh[1], bh[3]);
                }
            }
        }
    }

    // epilogue
    #pragma unroll
    for (int mf = 0; mf < 2; ++mf) {
        const int rlo = row0 + wm + mf * 16 + (lane >> 2);
        #pragma unroll
        for (int nf = 0; nf < 4; ++nf) {
            const int c = col0 + wn + nf * 8 + (lane & 3) * 2;
            const float bx = bias[c], by = bias[c + 1];
            #pragma unroll
            for (int hrow = 0; hrow < 2; ++hrow) {
                const int r = rlo + hrow * 8;
                if (r >= M) continue;
                float vx = acc[mf][nf][hrow * 2 + 0] + bx;
                float vy = acc[mf][nf][hrow * 2 + 1] + by;
                if (MODE == 0) {
                    const size_t po = (size_t)(r & (LL - 1)) * HH + c;
                    vx += pos[po];
                    vy += pos[po + 1];
                }
                if (MODE == 2) {
                    vx = (vx > 0.f) ? vx : 0.2f * vx;
                    vy = (vy > 0.f) ? vy : 0.2f * vy;
                }
                if (MODE == 1) {
                    *(__half2*)(Ch + (size_t)r * HH + c) = __floats2half2_rn(vx, vy);
                } else {
                    *(float2*)(Cf + (size_t)r * HH + c) = make_float2(vx, vy);
                }
            }
        }
    }
}

// ------------------- weight transpose -> fp16 -------------------------------
__global__ void wconv_kernel(const float* __restrict__ fc_w, const float* __restrict__ wq,
                             const float* __restrict__ wk, const float* __restrict__ wv,
                             const float* __restrict__ ring_wo)
{
    const int z = blockIdx.z;
    const float* W;
    if (z == 0) W = fc_w;
    else {
        const int s = z - 1, layer = s >> 2, which = s & 3;
        const float* base = (which == 0) ? wq : (which == 1) ? wk
                          : (which == 2) ? wv : ring_wo;
        W = base + (size_t)layer * HH * HH;
    }
    __shared__ float t[32][33];
    const int x0 = blockIdx.x * 32, y0 = blockIdx.y * 32;
    const int tx = threadIdx.x, ty = threadIdx.y;   // (32,8)
    #pragma unroll
    for (int i = 0; i < 4; ++i)
        t[ty * 4 + i][tx] = W[(size_t)(y0 + ty * 4 + i) * HH + x0 + tx];
    __syncthreads();
    __half* wh = g_wt + (size_t)z * HH * HH;
    #pragma unroll
    for (int i = 0; i < 4; ++i) {
        const int n = x0 + ty * 4 + i, k = y0 + tx;
        wh[(size_t)n * HH + k] = __float2half_rn(t[tx][ty * 4 + i]);
    }
}

// ----------------------- data -> fp16 conversion (2 halves) -----------------
__global__ void aconv_a_kernel(const float* __restrict__ x)
{
    const int n4 = BB * LL * HH / 8;
    for (int i = blockIdx.x * blockDim.x + threadIdx.x; i < n4;
         i += gridDim.x * blockDim.x) {
        const float4 v = *(const float4*)(x + (size_t)i * 4);
        __half h[4];
        h[0] = __float2half_rn(v.x); h[1] = __float2half_rn(v.y);
        h[2] = __float2half_rn(v.z); h[3] = __float2half_rn(v.w);
        *(uint2*)(g_data + (size_t)i * 4) = *(uint2*)h;
    }
}
__global__ void aconv_b_kernel(const float* __restrict__ x)
{
    const int half = BB * LL * HH / 8;
    const int n4 = BB * LL * HH / 4;
    for (int i = half + blockIdx.x * blockDim.x + threadIdx.x; i < n4;
         i += gridDim.x * blockDim.x) {
        const float4 v = *(const float4*)(x + (size_t)i * 4);
        __half h[4];
        h[0] = __float2half_rn(v.x); h[1] = __float2half_rn(v.y);
        h[2] = __float2half_rn(v.z); h[3] = __float2half_rn(v.w);
        *(uint2*)(g_data + (size_t)i * 4) = *(uint2*)h;
    }
}

// ------------------------- relay init (column mean) -------------------------
__global__ void colmean_partial()
{
    const int b = blockIdx.x, chunk = blockIdx.y, c = threadIdx.x;
    float s = 0.f;
    const int l0 = chunk * 128;
    for (int l = l0; l < l0 + 128; ++l)
        s += g_nodes[((size_t)b * LL + l) * HH + c];
    g_part[(b * 16 + chunk) * HH + c] = s;
}
__global__ void colmean_final()
{
    const int b = blockIdx.x, c = threadIdx.x;
    float s = 0.f;
    for (int t = 0; t < 16; ++t) s += g_part[(b * 16 + t) * HH + c];
    g_relay[b * HH + c] = s * (1.0f / (float)LL);
}

// ---------------- LayerNorm + concat relay -> fp16 --------------------------
__global__ void ln_concat_kernel(const float* __restrict__ gam, const float* __restrict__ bet)
{
    const int row = blockIdx.x;          // 0 .. B*2049-1
    const int b = row / LP1, l = row % LP1;
    const int tid = threadIdx.x;         // 128 threads, 4 floats each
    __half* oh = g_xy + (size_t)row * HH + tid * 4;

    float4 vv;
    if (l == LL) {
        vv = *(const float4*)(g_relay + b * HH + tid * 4);
        __half h[4];
        h[0] = __float2half_rn(vv.x); h[1] = __float2half_rn(vv.y);
        h[2] = __float2half_rn(vv.z); h[3] = __float2half_rn(vv.w);
        *(uint2*)oh = *(uint2*)h;
        return;
    }
    const float* x = g_nodes + ((size_t)b * LL + l) * HH;
    vv = *(const float4*)(x + tid * 4);
    float s  = vv.x + vv.y + vv.z + vv.w;
    float s2 = vv.x * vv.x + vv.y * vv.y + vv.z * vv.z + vv.w * vv.w;
    #pragma unroll
    for (int o = 16; o > 0; o >>= 1) {
        s  += __shfl_xor_sync(0xffffffffu, s,  o);
        s2 += __shfl_xor_sync(0xffffffffu, s2, o);
    }
    __shared__ float sh[8];
    const int wid = tid >> 5;
    if ((tid & 31) == 0) { sh[wid] = s; sh[4 + wid] = s2; }
    __syncthreads();
    const float S  = sh[0] + sh[1] + sh[2] + sh[3];
    const float S2 = sh[4] + sh[5] + sh[6] + sh[7];
    const float mu  = S * (1.0f / (float)HH);
    const float var = S2 * (1.0f / (float)HH) - mu * mu;
    const float inv = rsqrtf(var + 1e-6f);

    const float4 g4 = *(const float4*)(gam + tid * 4);
    const float4 b4 = *(const float4*)(bet + tid * 4);
    __half h[4];
    h[0] = __float2half_rn((vv.x - mu) * inv * g4.x + b4.x);
    h[1] = __float2half_rn((vv.y - mu) * inv * g4.y + b4.y);
    h[2] = __float2half_rn((vv.z - mu) * inv * g4.z + b4.z);
    h[3] = __float2half_rn((vv.w - mu) * inv * g4.w + b4.w);
    *(uint2*)oh = *(uint2*)h;
}

// -------------------- ring attention: 1 warp / (b,l,h), fp16 ----------------
__global__ void ring_attn_kernel()
{
    const int lane = threadIdx.x & 31;
    const int gw = blockIdx.x * (blockDim.x >> 5) + (threadIdx.x >> 5);
    const int h = gw & 7;
    const int l = (gw >> 3) & (LL - 1);
    const int b = gw >> 14;

    const int qoff = (b * LP1 + l) * HH + h * HD;
    const __half2 q2 = *(const __half2*)(g_q + qoff + 2 * lane);
    const float q0 = __low2float(q2), q1 = __high2float(q2);

    float s[4];
    int   koff[4];
    bool  ok[4];
    #pragma unroll
    for (int w = 0; w < 3; ++w) {
        const int lp = l - 1 + w;
        ok[w]   = (lp >= 0) && (lp < LL);
        koff[w] = (b * LP1 + lp) * HH + h * HD;
    }
    ok[3]   = true;
    koff[3] = (b * LP1 + LL) * HH + h * HD;

    #pragma unroll
    for (int w = 0; w < 4; ++w) {
        float p = 0.f;
        if (ok[w]) {
            const __half2 k2 = *(const __half2*)(g_k + koff[w] + 2 * lane);
            p = q0 * __low2float(k2) + q1 * __high2float(k2);
        }
        s[w] = p;
    }
    #pragma unroll
    for (int o = 16; o > 0; o >>= 1) {
        #pragma unroll
        for (int w = 0; w < 4; ++w)
            s[w] += __shfl_xor_sync(0xffffffffu, s[w], o);
    }
    #pragma unroll
    for (int w = 0; w < 4; ++w) s[w] *= 0.125f;
    float m = fmaxf(fmaxf(s[0], s[1]), fmaxf(s[2], s[3]));
    float e[4], sum = 0.f;
    #pragma unroll
    for (int w = 0; w < 4; ++w) { e[w] = expf(s[w] - m); sum += e[w]; }
    const float inv = 1.0f / sum;

    float a0 = 0.f, a1 = 0.f;
    #pragma unroll
    for (int w = 0; w < 4; ++w) {
        if (ok[w]) {
            const float al = e[w] * inv;
            const __half2 v2 = *(const __half2*)(g_v + koff[w] + 2 * lane);
            a0 += al * __low2float(v2);
            a1 += al * __high2float(v2);
        }
    }
    const int aoff = (b * LL + l) * HH + h * HD;
    *(__half2*)(g_att + aoff + 2 * lane) = __floats2half2_rn(a0, a1);
}

// --------------- star attention: 1 block / (b,h), 256 thr, fp16 -------------
__global__ void star_attn_kernel()
{
    const int b = blockIdx.x >> 3, h = blockIdx.x & 7;
    const int tid = threadIdx.x;

    __shared__ float sc[LP1];
    __shared__ float qs[HD];
    __shared__ float red[8];
    __shared__ float part[4][HD];
    __shared__ float s_m, s_inv;

    const int qrow = (b * LP1 + LL) * HH + h * HD;
    if (tid < HD) qs[tid] = __half2float(g_q[qrow + tid]);
    __syncthreads();

    for (int j = tid; j < LP1; j += 256) {
        const __half2* kp = (const __half2*)(g_k + ((size_t)(b * LP1 + j)) * HH + h * HD);
        float s = 0.f;
        #pragma unroll
        for (int d = 0; d < HD / 2; ++d) {
            const __half2 k2 = kp[d];
            s += qs[2 * d] * __low2float(k2) + qs[2 * d + 1] * __high2float(k2);
        }
        sc[j] = s * 0.125f;
    }
    __syncthreads();

    float m = -3.4e38f;
    for (int j = tid; j < LP1; j += 256) m = fmaxf(m, sc[j]);
    #pragma unroll
    for (int o = 16; o > 0; o >>= 1) m = fmaxf(m, __shfl_xor_sync(0xffffffffu, m, o));
    if ((tid & 31) == 0) red[tid >> 5] = m;
    __syncthreads();
    if (tid == 0) {
        float mm = red[0];
        for (int w = 1; w < 8; ++w) mm = fmaxf(mm, red[w]);
        s_m = mm;
    }
    __syncthreads();
    m = s_m;

    float sum = 0.f;
    for (int j = tid; j < LP1; j += 256) {
        const float e = expf(sc[j] - m);
        sc[j] = e;
        sum += e;
    }
    #pragma unroll
    for (int o = 16; o > 0; o >>= 1) sum += __shfl_xor_sync(0xffffffffu, sum, o);
    __syncthreads();
    if ((tid & 31) == 0) red[tid >> 5] = sum;
    __syncthreads();
    if (tid == 0) {
        float ss = 0.f;
        for (int w = 0; w < 8; ++w) ss += red[w];
        s_inv = 1.0f / ss;
    }
    __syncthreads();
    const float inv = s_inv;

    const int g = tid >> 6, d = tid & 63;
    float acc = 0.f;
    for (int j = g; j < LP1; j += 4)
        acc += sc[j] * __half2float(g_v[((size_t)(b * LP1 + j)) * HH + h * HD + d]);
    part[g][d] = acc;
    __syncthreads();
    if (tid < HD) {
        const float r = (part[0][tid] + part[1][tid] + part[2][tid] + part[3][tid]) * inv;
        g_attr[b * HH + h * HD + tid] = r;
    }
}

// ------------------- star output projection (tiny GEMM) ---------------------
__global__ void star_out_kernel(const float* __restrict__ wo, const float* __restrict__ bo)
{
    const int b = blockIdx.x, c = threadIdx.x;
    __shared__ float a[HH];
    a[c] = g_attr[b * HH + c];
    __syncthreads();
    float s = bo[c];
    #pragma unroll 8
    for (int d = 0; d < HH; ++d) s += a[d] * wo[d * HH + c];
    g_relay[b * HH + c] = (s > 0.f) ? s : 0.2f * s;
}

// -------------------------- final: max + combine ----------------------------
__global__ void maxred_partial()
{
    const int b = blockIdx.x, chunk = blockIdx.y, c = threadIdx.x;
    float m = -3.4e38f;
    const int l0 = chunk * 128;
    for (int l = l0; l < l0 + 128; ++l)
        m = fmaxf(m, g_nodes[((size_t)b * LL + l) * HH + c]);
    g_part[(b * 16 + chunk) * HH + c] = m;
}
__global__ void final_out_kernel(float* __restrict__ out)
{
    const int b = blockIdx.x, c = threadIdx.x;
    float m = -3.4e38f;
    for (int t = 0; t < 16; ++t) m = fmaxf(m, g_part[(b * 16 + t) * HH + c]);
    out[b * HH + c] = 0.5f * (g_relay[b * HH + c] + m);
}

// ------------------------------- host driver --------------------------------
extern "C" void kernel_launch(void* const* d_in, const int* in_sizes, int n_in,
                              void* d_out, int out_size)
{
    const float* data    = (const float*)d_in[0];
    const float* fc_w    = (const float*)d_in[1];
    const float* fc_b    = (const float*)d_in[2];
    const float* pos_emb = (const float*)d_in[3];
    const float* ln_g    = (const float*)d_in[4];
    const float* ln_b    = (const float*)d_in[5];
    const float* wq      = (const float*)d_in[6];
    const float* wk      = (const float*)d_in[7];
    const float* wv      = (const float*)d_in[8];
    const float* bq      = (const float*)d_in[9];
    const float* bk      = (const float*)d_in[10];
    const float* bv      = (const float*)d_in[11];
    const float* ring_wo = (const float*)d_in[12];
    const float* ring_bo = (const float*)d_in[13];
    const float* star_wo = (const float*)d_in[14];
    const float* star_bo = (const float*)d_in[15];
    float* out = (float*)d_out;

    static cudaStream_t s2;
    static cudaEvent_t evFork[NL], evJoin[NL];
    static bool init_done = false;
    if (!init_done) {
        cudaFuncSetAttribute(mma_gemm<0>, cudaFuncAttributeMaxDynamicSharedMemorySize, GEMM_SMEM);
        cudaFuncSetAttribute(mma_gemm<1>, cudaFuncAttributeMaxDynamicSharedMemorySize, GEMM_SMEM);
        cudaFuncSetAttribute(mma_gemm<2>, cudaFuncAttributeMaxDynamicSharedMemorySize, GEMM_SMEM);
        cudaStreamCreateWithFlags(&s2, cudaStreamNonBlocking);
        for (int i = 0; i < NL; ++i) {
            cudaEventCreateWithFlags(&evFork[i], cudaEventDisableTiming);
            cudaEventCreateWithFlags(&evJoin[i], cudaEventDisableTiming);
        }
        init_done = true;
    }

    const int M_full = BB * LL;    // 16384
    const int M_xy   = BB * LP1;   // 16392
    const dim3 gFull(8, M_full / 128);              // (8,128)
    const dim3 gQKV (8, (M_xy + 127) / 128, 3);     // (8,129,3)

    // one-time per-call conversions
    wconv_kernel<<<dim3(16, 16, NSLOT), dim3(32, 8)>>>(fc_w, wq, wk, wv, ring_wo);
    aconv_a_kernel<<<2048, 256>>>(data);
    aconv_b_kernel<<<2048, 256>>>(data);

    // embedding: nodes = data @ fc_w + fc_b + pos_emb
    mma_gemm<0><<<gFull, 256, GEMM_SMEM>>>(0, M_full, fc_b, nullptr, nullptr, pos_emb);

    colmean_partial<<<dim3(BB, 16), HH>>>();
    colmean_final<<<BB, HH>>>();

    for (int i = 0; i < NL; ++i) {
        const int wOff = i * HH * HH;
        const int bOff = i * HH;

        ln_concat_kernel<<<M_xy, 128>>>(ln_g + bOff, ln_b + bOff);

        mma_gemm<1><<<gQKV, 256, GEMM_SMEM>>>(i, M_xy, bq + bOff, bk + bOff,
                                              bv + bOff, nullptr);

        // fork: star branch (star_attn -> star_out) on s2, overlapping
        // the ring branch (ring_attn -> mode2 GEMM) on the main stream.
        cudaEventRecord(evFork[i], 0);
        cudaStreamWaitEvent(s2, evFork[i], 0);
        star_attn_kernel<<<BB * NHD, 256, 0, s2>>>();
        star_out_kernel<<<BB, HH, 0, s2>>>(star_wo + wOff, star_bo + bOff);
        cudaEventRecord(evJoin[i], s2);

        ring_attn_kernel<<<(BB * LL * NHD) / 8, 256>>>();
        mma_gemm<2><<<gFull, 256, GEMM_SMEM>>>(i, M_full, ring_bo + bOff,
                                               nullptr, nullptr, nullptr);

        // join before next layer's ln_concat (needs relay)
        cudaStreamWaitEvent(0, evJoin[i], 0);
    }

    maxred_partial<<<dim3(BB, 16), HH>>>();
    final_out_kernel<<<BB, HH>>>(out);
}